// round 5
// baseline (speedup 1.0000x reference)
#include <cuda_runtime.h>

#define Hh 256
#define Ww 704
#define HW (Hh*Ww)      // 180224 = 176*256*4
#define W4 (Ww/4)       // 176
#define CIMG 256
#define COUTC 131

// Scratch (device globals; no allocation allowed)
__device__ float4 d_gpart4[8 * (HW/4)];   // 8 channel-slab partial sums of gated
__device__ float d_spt[HW];
__device__ float4 d_att4[HW/4];
__device__ float d_v2[9*COUTC];
__device__ float d_u0[9*35];
__device__ float d_u1[9*67];
__device__ float d_wg[9];
__device__ float d_Ksum[9];               // [rowclass*3+colclass] bias sums

// ---------------------------------------------------------------------------
// Fold weights:
// v2[t][j] = sum_c sp_w[c][t]*rd2_w[c][j]
// u0[t][i] = sum_j v2[t][j]*rd0_w[j][i]   (u1 analogous)
// wg[t]    = sum_c sp_w[c][t]
// K[t]     = sum_j v2[t][j]*(rd0_b[j]+rd1_b[j]) + sum_c sp_w[c][t]*rd2_b[c] + wg[t]*rd3_b
// Ksum[rc*3+cc] = sum of K[t] over taps in-bounds for that row/col class
// ---------------------------------------------------------------------------
__global__ void fold_kernel(const float* __restrict__ sp_w,
                            const float* __restrict__ rd0_w,
                            const float* __restrict__ rd1_w,
                            const float* __restrict__ rd0_b,
                            const float* __restrict__ rd1_b,
                            const float* __restrict__ rd2_w,
                            const float* __restrict__ rd2_b,
                            const float* __restrict__ rd3_b) {
    int tid = threadIdx.x;
    __shared__ float sK[9];
    for (int idx = tid; idx < 9*COUTC; idx += blockDim.x) {
        int t = idx / COUTC, j = idx % COUTC;
        float a = 0.f;
        for (int c = 0; c < COUTC; ++c) a += sp_w[c*9 + t] * rd2_w[c*COUTC + j];
        d_v2[idx] = a;
    }
    __syncthreads();
    for (int idx = tid; idx < 9*35; idx += blockDim.x) {
        int t = idx / 35, i = idx % 35;
        float a = 0.f;
        for (int j = 0; j < COUTC; ++j) a += d_v2[t*COUTC + j] * rd0_w[j*35 + i];
        d_u0[idx] = a;
    }
    for (int idx = tid; idx < 9*67; idx += blockDim.x) {
        int t = idx / 67, i = idx % 67;
        float a = 0.f;
        for (int j = 0; j < COUTC; ++j) a += d_v2[t*COUTC + j] * rd1_w[j*67 + i];
        d_u1[idx] = a;
    }
    if (tid < 9) {
        int t = tid;
        float w = 0.f, k = 0.f;
        for (int c = 0; c < COUTC; ++c) {
            w += sp_w[c*9 + t];
            k += d_v2[t*COUTC + c] * (rd0_b[c] + rd1_b[c]) + sp_w[c*9 + t] * rd2_b[c];
        }
        d_wg[t] = w;
        sK[t]   = k + w * rd3_b[0];
    }
    __syncthreads();
    if (tid < 9) {
        int rc = tid / 3, cc = tid % 3;
        float s = 0.f;
        for (int ty = 0; ty < 3; ++ty) {
            if ((rc == 0 && ty == 0) || (rc == 2 && ty == 2)) continue;
            for (int tx = 0; tx < 3; ++tx) {
                if ((cc == 0 && tx == 0) || (cc == 2 && tx == 2)) continue;
                s += sK[ty*3 + tx];
            }
        }
        d_Ksum[tid] = s;
    }
}

__global__ void zero_kernel() {
    ((float4*)d_spt)[blockIdx.x * 256 + threadIdx.x] = make_float4(0.f,0.f,0.f,0.f);
}

// ---------------------------------------------------------------------------
// Gated slabs: grid (176, 8); slab s = blockIdx.y covers channels [32s, 32s+32).
// Pure streaming reduce, no atomics, no init dependency.
// ---------------------------------------------------------------------------
__global__ void gated_kernel(const float* __restrict__ img,
                             const float* __restrict__ rd3_w) {
    __shared__ float sw[32];
    int c0 = blockIdx.y * 32;
    if (threadIdx.x < 32) sw[threadIdx.x] = rd3_w[c0 + threadIdx.x];
    __syncthreads();
    int p4 = blockIdx.x * 256 + threadIdx.x;
    const float4* base = (const float4*)img + (size_t)c0 * (HW/4) + p4;
    float4 acc = make_float4(0.f, 0.f, 0.f, 0.f);
    #pragma unroll
    for (int c = 0; c < 32; ++c) {
        float w = sw[c];
        float4 x = __ldcs(base + (size_t)c * (HW/4));
        acc.x += w * x.x; acc.y += w * x.y; acc.z += w * x.z; acc.w += w * x.w;
    }
    d_gpart4[blockIdx.y * (HW/4) + p4] = acc;
}

// ---------------------------------------------------------------------------
// Scatter: warp = 3 points x 9 taps; per-lane dot product + one atomicAdd.
// ---------------------------------------------------------------------------
template<int CF>
__device__ __forceinline__ void scatter_level(const float* __restrict__ feat,
                                              const float* __restrict__ coord,
                                              const int* __restrict__ grid,
                                              int N, const float* __restrict__ u,
                                              int blockInLevel, int blocksInLevel) {
    constexpr int L  = CF + 3;
    constexpr int LP = CF + 4;
    __shared__ __align__(16) float su[9 * LP];
    for (int idx = threadIdx.x; idx < 9 * L; idx += blockDim.x) {
        int t = idx / L, i = idx - t * L;
        su[t * LP + i] = u[idx];
    }
    __syncthreads();
    int warpsPerBlock = blockDim.x >> 5;
    int warpInLevel = blockInLevel * warpsPerBlock + (threadIdx.x >> 5);
    int nwarps = blocksInLevel * warpsPerBlock;
    int lane = threadIdx.x & 31;
    int g = lane / 9;
    int t = lane - g * 9;
    bool laneActive = lane < 27;
    const float* surow = &su[t * LP];
    for (int base = warpInLevel * 3; base < N; base += nwarps * 3) {
        int n = base + g;
        if (laneActive && n < N) {
            const float4* fp = (const float4*)(feat + (size_t)n * CF);
            float4 a = make_float4(0.f, 0.f, 0.f, 0.f);
            #pragma unroll
            for (int j = 0; j < CF / 4; ++j) {
                float4 p = __ldg(fp + j);
                float4 w = *(const float4*)(surow + 4 * j);
                a.x += w.x * p.x; a.y += w.y * p.y;
                a.z += w.z * p.z; a.w += w.w * p.w;
            }
            float ac = (a.x + a.y) + (a.z + a.w);
            ac += surow[CF + 0] * __ldg(coord + n * 3 + 0);
            ac += surow[CF + 1] * __ldg(coord + n * 3 + 1);
            ac += surow[CF + 2] * __ldg(coord + n * 3 + 2);
            int2 gxy = __ldg((const int2*)grid + n);       // (col, row)
            int h = gxy.y - t / 3 + 1;
            int w = gxy.x - t % 3 + 1;
            if (h >= 0 && h < Hh && w >= 0 && w < Ww)
                atomicAdd(&d_spt[h * Ww + w], ac);
        }
    }
}

#define B0 280
#define B1 430
#define B2 630

__global__ void scatter_kernel(const float* __restrict__ f0, const float* __restrict__ c0,
                               const int* __restrict__ g0, int N0,
                               const float* __restrict__ f1, const float* __restrict__ c1,
                               const int* __restrict__ g1, int N1,
                               const float* __restrict__ f2, const float* __restrict__ c2,
                               const int* __restrict__ g2, int N2) {
    int b = blockIdx.x;
    if (b < B0) {
        scatter_level<32>(f0, c0, g0, N0, d_u0, b, B0);
    } else if (b < B0 + B1) {
        scatter_level<64>(f1, c1, g1, N1, d_u1, b - B0, B1);
    } else {
        scatter_level<128>(f2, c2, g2, N2, d_v2, b - B0 - B1, B2);
    }
}

// ---------------------------------------------------------------------------
// att: one row per block (176 threads). Sum 8 slabs for rows h-1..h+1 into a
// smem stencil buffer, then 9-tap with wg + boundary Ksum, sigmoid.
// ---------------------------------------------------------------------------
__global__ void att_kernel(const float* __restrict__ sp_b) {
    __shared__ __align__(16) float sm[3][712];   // cols at [4 .. 708), halos at 3 / 708
    __shared__ float swg[9], sks[9];
    int h = blockIdx.x, t = threadIdx.x;
    if (t < 9)  swg[t] = d_wg[t];
    else if (t < 18) sks[t - 9] = d_Ksum[t - 9];
    #pragma unroll
    for (int r = 0; r < 3; ++r) {
        int y = h + r - 1;
        float4 s = make_float4(0.f, 0.f, 0.f, 0.f);
        if (y >= 0 && y < Hh) {
            #pragma unroll
            for (int sl = 0; sl < 8; ++sl) {
                float4 v = __ldg(&d_gpart4[sl * (HW/4) + y * W4 + t]);
                s.x += v.x; s.y += v.y; s.z += v.z; s.w += v.w;
            }
        }
        *(float4*)&sm[r][4 + 4*t] = s;
        if (t == 0) { sm[r][3] = 0.f; sm[r][708] = 0.f; }
    }
    __syncthreads();
    float bias = sp_b[0];
    int rc = (h == 0) ? 0 : (h == Hh-1 ? 2 : 1);
    float4 spt = ((const float4*)d_spt)[h * W4 + t];
    float sptv[4] = {spt.x, spt.y, spt.z, spt.w};
    float res[4];
    #pragma unroll
    for (int i = 0; i < 4; ++i) {
        int col = 4*t + i;
        int cc = (col == 0) ? 0 : (col == Ww-1 ? 2 : 1);
        float s = bias + sptv[i] + sks[rc*3 + cc];
        #pragma unroll
        for (int t9 = 0; t9 < 9; ++t9) {
            int dy = t9 / 3, dx = t9 % 3;
            s += swg[t9] * sm[dy][4 + col + dx - 1];
        }
        res[i] = 1.f / (1.f + __expf(-s));
    }
    d_att4[h * W4 + t] = make_float4(res[0], res[1], res[2], res[3]);
}

// ---------------------------------------------------------------------------
// out[c][p] = img[c][p] * att[p]; grid (176, 8), 32 channels per block.
// ---------------------------------------------------------------------------
__global__ void mul_kernel(const float* __restrict__ img, float* __restrict__ out) {
    int p4 = blockIdx.x * 256 + threadIdx.x;
    float4 a = __ldg(&d_att4[p4]);
    size_t off = (size_t)blockIdx.y * 32 * (HW/4) + p4;
    const float4* img4 = (const float4*)img;
    float4* out4 = (float4*)out;
    #pragma unroll 8
    for (int c = 0; c < 32; ++c) {
        float4 v = __ldcs(&img4[off + (size_t)c * (HW/4)]);
        float4 r = make_float4(v.x * a.x, v.y * a.y, v.z * a.z, v.w * a.w);
        __stcs(&out4[off + (size_t)c * (HW/4)], r);
    }
}

extern "C" void kernel_launch(void* const* d_in, const int* in_sizes, int n_in,
                              void* d_out, int out_size) {
    const float* img   = (const float*)d_in[0];
    const float* f0    = (const float*)d_in[1];
    const float* c0    = (const float*)d_in[2];
    const int*   g0    = (const int*)  d_in[3];
    const float* f1    = (const float*)d_in[4];
    const float* c1    = (const float*)d_in[5];
    const int*   g1    = (const int*)  d_in[6];
    const float* f2    = (const float*)d_in[7];
    const float* c2    = (const float*)d_in[8];
    const int*   g2    = (const int*)  d_in[9];
    const float* rd0_w = (const float*)d_in[10];
    const float* rd0_b = (const float*)d_in[11];
    const float* rd1_w = (const float*)d_in[12];
    const float* rd1_b = (const float*)d_in[13];
    const float* rd2_w = (const float*)d_in[14];
    const float* rd2_b = (const float*)d_in[15];
    const float* rd3_w = (const float*)d_in[16];
    const float* rd3_b = (const float*)d_in[17];
    const float* sp_w  = (const float*)d_in[18];
    const float* sp_b  = (const float*)d_in[19];

    int N0 = in_sizes[1] / 32;
    int N1 = in_sizes[4] / 64;
    int N2 = in_sizes[7] / 128;

    // Launch order chosen so the 4th launch (profiled by ncu) is scatter_kernel.
    fold_kernel<<<1, 512>>>(sp_w, rd0_w, rd1_w, rd0_b, rd1_b, rd2_w, rd2_b, rd3_b);
    zero_kernel<<<176, 256>>>();
    gated_kernel<<<dim3(176, 8), 256>>>(img, rd3_w);
    scatter_kernel<<<B0 + B1 + B2, 256>>>(f0, c0, g0, N0,
                                          f1, c1, g1, N1,
                                          f2, c2, g2, N2);
    att_kernel<<<Hh, 176>>>(sp_b);
    mul_kernel<<<dim3(176, 8), 256>>>(img, (float*)d_out);
}

// round 6
// speedup vs baseline: 1.1811x; 1.1811x over previous
#include <cuda_runtime.h>

#define Hh 256
#define Ww 704
#define HW (Hh*Ww)      // 180224 = 176*256*4
#define W4 (Ww/4)       // 176
#define CIMG 256
#define COUTC 131

// Scratch (device globals; no allocation allowed)
__device__ float4 d_gpart4[8 * (HW/4)];   // 8 channel-slab partial sums of gated
__device__ float d_spt[HW];
__device__ float4 d_att4[HW/4];
__device__ float d_v2[9*COUTC];
__device__ float d_u0[9*35];
__device__ float d_u1[9*67];
__device__ float d_wg[9];
__device__ float d_Ksum[9];               // [rowclass*3+colclass] bias sums

// ---------------------------------------------------------------------------
// Setup: block 0 folds weights, blocks 1..88 zero d_spt (512 threads each).
// ---------------------------------------------------------------------------
__global__ void setup_kernel(const float* __restrict__ sp_w,
                             const float* __restrict__ rd0_w,
                             const float* __restrict__ rd1_w,
                             const float* __restrict__ rd0_b,
                             const float* __restrict__ rd1_b,
                             const float* __restrict__ rd2_w,
                             const float* __restrict__ rd2_b,
                             const float* __restrict__ rd3_b) {
    int tid = threadIdx.x;
    if (blockIdx.x > 0) {
        int idx = (blockIdx.x - 1) * 512 + tid;
        if (idx < HW/4)
            ((float4*)d_spt)[idx] = make_float4(0.f, 0.f, 0.f, 0.f);
        return;
    }
    __shared__ float sK[9];
    for (int idx = tid; idx < 9*COUTC; idx += blockDim.x) {
        int t = idx / COUTC, j = idx % COUTC;
        float a = 0.f;
        for (int c = 0; c < COUTC; ++c) a += sp_w[c*9 + t] * rd2_w[c*COUTC + j];
        d_v2[idx] = a;
    }
    __syncthreads();
    for (int idx = tid; idx < 9*35; idx += blockDim.x) {
        int t = idx / 35, i = idx % 35;
        float a = 0.f;
        for (int j = 0; j < COUTC; ++j) a += d_v2[t*COUTC + j] * rd0_w[j*35 + i];
        d_u0[idx] = a;
    }
    for (int idx = tid; idx < 9*67; idx += blockDim.x) {
        int t = idx / 67, i = idx % 67;
        float a = 0.f;
        for (int j = 0; j < COUTC; ++j) a += d_v2[t*COUTC + j] * rd1_w[j*67 + i];
        d_u1[idx] = a;
    }
    if (tid < 9) {
        int t = tid;
        float w = 0.f, k = 0.f;
        for (int c = 0; c < COUTC; ++c) {
            w += sp_w[c*9 + t];
            k += d_v2[t*COUTC + c] * (rd0_b[c] + rd1_b[c]) + sp_w[c*9 + t] * rd2_b[c];
        }
        d_wg[t] = w;
        sK[t]   = k + w * rd3_b[0];
    }
    __syncthreads();
    if (tid < 9) {
        int rc = tid / 3, cc = tid % 3;
        float s = 0.f;
        for (int ty = 0; ty < 3; ++ty) {
            if ((rc == 0 && ty == 0) || (rc == 2 && ty == 2)) continue;
            for (int tx = 0; tx < 3; ++tx) {
                if ((cc == 0 && tx == 0) || (cc == 2 && tx == 2)) continue;
                s += sK[ty*3 + tx];
            }
        }
        d_Ksum[tid] = s;
    }
}

// ---------------------------------------------------------------------------
// Gated slabs: slab s covers channels [32s, 32s+32); pure streaming reduce.
// ---------------------------------------------------------------------------
__device__ __forceinline__ void gated_part(const float* __restrict__ img,
                                           const float* __restrict__ rd3_w,
                                           int b) {
    __shared__ float sw[32];
    int pb = b % 176, cb = b / 176;
    int c0 = cb * 32;
    if (threadIdx.x < 32) sw[threadIdx.x] = rd3_w[c0 + threadIdx.x];
    __syncthreads();
    int p4 = pb * 256 + threadIdx.x;
    const float4* base = (const float4*)img + (size_t)c0 * (HW/4) + p4;
    float4 acc = make_float4(0.f, 0.f, 0.f, 0.f);
    #pragma unroll
    for (int c = 0; c < 32; ++c) {
        float w = sw[c];
        float4 x = __ldcs(base + (size_t)c * (HW/4));
        acc.x += w * x.x; acc.y += w * x.y; acc.z += w * x.z; acc.w += w * x.w;
    }
    d_gpart4[cb * (HW/4) + p4] = acc;
}

// ---------------------------------------------------------------------------
// Scatter, thread-per-point: each thread loads its own feature row once
// (float4, minimal L1 traffic), tap weights come from smem float4 BROADCASTS
// (suT[j*9+t] = u[t][4j..4j+3], coords padded into the last chunk).
// 9 spread-address atomicAdds per point.
// ---------------------------------------------------------------------------
template<int CF>
__device__ __forceinline__ void scatter_level(const float* __restrict__ feat,
                                              const float* __restrict__ coord,
                                              const int* __restrict__ grid,
                                              int N, const float* __restrict__ u,
                                              int blockInLevel) {
    constexpr int L  = CF + 3;
    constexpr int NC = CF/4 + 1;               // float4 chunks incl. coord tail
    __shared__ __align__(16) float4 suT[NC * 9];
    for (int idx = threadIdx.x; idx < NC * 9 * 4; idx += blockDim.x) {
        int c = idx & 3, jt = idx >> 2;
        int t = jt % 9, j = jt / 9;
        int i = 4 * j + c;
        ((float*)&suT[j * 9 + t])[c] = (i < L) ? u[t * L + i] : 0.f;
    }
    __syncthreads();
    int n = blockInLevel * 256 + threadIdx.x;
    if (n >= N) return;
    float acc[9];
    #pragma unroll
    for (int t = 0; t < 9; ++t) acc[t] = 0.f;
    const float4* fp = (const float4*)(feat + (size_t)n * CF);
    #pragma unroll
    for (int j = 0; j < CF/4; ++j) {
        float4 p = __ldg(fp + j);
        #pragma unroll
        for (int t = 0; t < 9; ++t) {
            float4 w = suT[j * 9 + t];
            acc[t] += w.x*p.x + w.y*p.y + w.z*p.z + w.w*p.w;
        }
    }
    float c0 = __ldg(coord + n*3 + 0);
    float c1 = __ldg(coord + n*3 + 1);
    float c2 = __ldg(coord + n*3 + 2);
    #pragma unroll
    for (int t = 0; t < 9; ++t) {
        float4 w = suT[(CF/4) * 9 + t];
        acc[t] += w.x*c0 + w.y*c1 + w.z*c2;
    }
    int2 gxy = __ldg((const int2*)grid + n);   // (col, row)
    #pragma unroll
    for (int t = 0; t < 9; ++t) {
        int h = gxy.y - t/3 + 1;
        int w = gxy.x - t%3 + 1;
        if (h >= 0 && h < Hh && w >= 0 && w < Ww)
            atomicAdd(&d_spt[h * Ww + w], acc[t]);
    }
}

#define GB 1408   // gated blocks (176 x 8)

// Combined gated + scatter: independent inputs/outputs, one launch.
__global__ void work_kernel(const float* __restrict__ img, const float* __restrict__ rd3_w,
                            const float* __restrict__ f0, const float* __restrict__ c0,
                            const int* __restrict__ g0, int N0,
                            const float* __restrict__ f1, const float* __restrict__ c1,
                            const int* __restrict__ g1, int N1,
                            const float* __restrict__ f2, const float* __restrict__ c2,
                            const int* __restrict__ g2, int N2,
                            int sb0, int sb1, int sb2) {
    int b = blockIdx.x;
    if (b < GB) {
        gated_part(img, rd3_w, b);
    } else if (b < GB + sb0) {
        scatter_level<32>(f0, c0, g0, N0, d_u0, b - GB);
    } else if (b < GB + sb0 + sb1) {
        scatter_level<64>(f1, c1, g1, N1, d_u1, b - GB - sb0);
    } else {
        scatter_level<128>(f2, c2, g2, N2, d_v2, b - GB - sb0 - sb1);
    }
}

// ---------------------------------------------------------------------------
// att: one row per block (176 threads). Sum 8 slabs for rows h-1..h+1 into a
// smem stencil buffer, then 9-tap with wg + boundary Ksum, sigmoid.
// ---------------------------------------------------------------------------
__global__ void att_kernel(const float* __restrict__ sp_b) {
    __shared__ __align__(16) float sm[3][712];   // cols at [4 .. 708)
    __shared__ float swg[9], sks[9];
    int h = blockIdx.x, t = threadIdx.x;
    if (t < 9)  swg[t] = d_wg[t];
    else if (t < 18) sks[t - 9] = d_Ksum[t - 9];
    #pragma unroll
    for (int r = 0; r < 3; ++r) {
        int y = h + r - 1;
        float4 s = make_float4(0.f, 0.f, 0.f, 0.f);
        if (y >= 0 && y < Hh) {
            #pragma unroll
            for (int sl = 0; sl < 8; ++sl) {
                float4 v = __ldg(&d_gpart4[sl * (HW/4) + y * W4 + t]);
                s.x += v.x; s.y += v.y; s.z += v.z; s.w += v.w;
            }
        }
        *(float4*)&sm[r][4 + 4*t] = s;
        if (t == 0) { sm[r][3] = 0.f; sm[r][708] = 0.f; }
    }
    __syncthreads();
    float bias = sp_b[0];
    int rc = (h == 0) ? 0 : (h == Hh-1 ? 2 : 1);
    float4 spt = ((const float4*)d_spt)[h * W4 + t];
    float sptv[4] = {spt.x, spt.y, spt.z, spt.w};
    float res[4];
    #pragma unroll
    for (int i = 0; i < 4; ++i) {
        int col = 4*t + i;
        int cc = (col == 0) ? 0 : (col == Ww-1 ? 2 : 1);
        float s = bias + sptv[i] + sks[rc*3 + cc];
        #pragma unroll
        for (int t9 = 0; t9 < 9; ++t9) {
            int dy = t9 / 3, dx = t9 % 3;
            s += swg[t9] * sm[dy][4 + col + dx - 1];
        }
        res[i] = 1.f / (1.f + __expf(-s));
    }
    d_att4[h * W4 + t] = make_float4(res[0], res[1], res[2], res[3]);
}

// ---------------------------------------------------------------------------
// out[c][p] = img[c][p] * att[p]; grid (176, 8), 32 channels per block.
// ---------------------------------------------------------------------------
__global__ void mul_kernel(const float* __restrict__ img, float* __restrict__ out) {
    int p4 = blockIdx.x * 256 + threadIdx.x;
    float4 a = __ldg(&d_att4[p4]);
    size_t off = (size_t)blockIdx.y * 32 * (HW/4) + p4;
    const float4* img4 = (const float4*)img;
    float4* out4 = (float4*)out;
    #pragma unroll 8
    for (int c = 0; c < 32; ++c) {
        float4 v = __ldcs(&img4[off + (size_t)c * (HW/4)]);
        float4 r = make_float4(v.x * a.x, v.y * a.y, v.z * a.z, v.w * a.w);
        __stcs(&out4[off + (size_t)c * (HW/4)], r);
    }
}

extern "C" void kernel_launch(void* const* d_in, const int* in_sizes, int n_in,
                              void* d_out, int out_size) {
    const float* img   = (const float*)d_in[0];
    const float* f0    = (const float*)d_in[1];
    const float* c0    = (const float*)d_in[2];
    const int*   g0    = (const int*)  d_in[3];
    const float* f1    = (const float*)d_in[4];
    const float* c1    = (const float*)d_in[5];
    const int*   g1    = (const int*)  d_in[6];
    const float* f2    = (const float*)d_in[7];
    const float* c2    = (const float*)d_in[8];
    const int*   g2    = (const int*)  d_in[9];
    const float* rd0_w = (const float*)d_in[10];
    const float* rd0_b = (const float*)d_in[11];
    const float* rd1_w = (const float*)d_in[12];
    const float* rd1_b = (const float*)d_in[13];
    const float* rd2_w = (const float*)d_in[14];
    const float* rd2_b = (const float*)d_in[15];
    const float* rd3_w = (const float*)d_in[16];
    const float* rd3_b = (const float*)d_in[17];
    const float* sp_w  = (const float*)d_in[18];
    const float* sp_b  = (const float*)d_in[19];

    int N0 = in_sizes[1] / 32;
    int N1 = in_sizes[4] / 64;
    int N2 = in_sizes[7] / 128;
    int sb0 = (N0 + 255) / 256;
    int sb1 = (N1 + 255) / 256;
    int sb2 = (N2 + 255) / 256;

    setup_kernel<<<1 + (HW/4 + 511)/512, 512>>>(sp_w, rd0_w, rd1_w, rd0_b, rd1_b,
                                                rd2_w, rd2_b, rd3_b);
    work_kernel<<<GB + sb0 + sb1 + sb2, 256>>>(img, rd3_w,
                                               f0, c0, g0, N0,
                                               f1, c1, g1, N1,
                                               f2, c2, g2, N2,
                                               sb0, sb1, sb2);
    att_kernel<<<Hh, 176>>>(sp_b);
    mul_kernel<<<dim3(176, 8), 256>>>(img, (float*)d_out);
}

// round 7
// speedup vs baseline: 1.2871x; 1.0897x over previous
#include <cuda_runtime.h>

#define Hh 256
#define Ww 704
#define HW (Hh*Ww)      // 180224 = 176*256*4
#define W4 (Ww/4)       // 176
#define CIMG 256
#define COUTC 131

// Scratch (device globals; no allocation allowed)
__device__ float4 d_gpart4[8 * (HW/4)];   // 8 channel-slab partial sums of gated
__device__ float d_spt[HW];
__device__ float4 d_att4[HW/4];
__device__ float d_v2[9*COUTC];
__device__ float d_u0[9*35];
__device__ float d_u1[9*67];
__device__ float d_wg[9];
__device__ float d_Ksum[9];               // [rowclass*3+colclass] bias sums

// ---------------------------------------------------------------------------
// Setup: block 0 folds weights, blocks 1..89 zero d_spt (512 threads each).
// ---------------------------------------------------------------------------
__global__ void setup_kernel(const float* __restrict__ sp_w,
                             const float* __restrict__ rd0_w,
                             const float* __restrict__ rd1_w,
                             const float* __restrict__ rd0_b,
                             const float* __restrict__ rd1_b,
                             const float* __restrict__ rd2_w,
                             const float* __restrict__ rd2_b,
                             const float* __restrict__ rd3_b) {
    int tid = threadIdx.x;
    if (blockIdx.x > 0) {
        int idx = (blockIdx.x - 1) * 512 + tid;
        if (idx < HW/4)
            ((float4*)d_spt)[idx] = make_float4(0.f, 0.f, 0.f, 0.f);
        return;
    }
    __shared__ float sK[9];
    for (int idx = tid; idx < 9*COUTC; idx += blockDim.x) {
        int t = idx / COUTC, j = idx % COUTC;
        float a = 0.f;
        for (int c = 0; c < COUTC; ++c) a += sp_w[c*9 + t] * rd2_w[c*COUTC + j];
        d_v2[idx] = a;
    }
    __syncthreads();
    for (int idx = tid; idx < 9*35; idx += blockDim.x) {
        int t = idx / 35, i = idx % 35;
        float a = 0.f;
        for (int j = 0; j < COUTC; ++j) a += d_v2[t*COUTC + j] * rd0_w[j*35 + i];
        d_u0[idx] = a;
    }
    for (int idx = tid; idx < 9*67; idx += blockDim.x) {
        int t = idx / 67, i = idx % 67;
        float a = 0.f;
        for (int j = 0; j < COUTC; ++j) a += d_v2[t*COUTC + j] * rd1_w[j*67 + i];
        d_u1[idx] = a;
    }
    if (tid < 9) {
        int t = tid;
        float w = 0.f, k = 0.f;
        for (int c = 0; c < COUTC; ++c) {
            w += sp_w[c*9 + t];
            k += d_v2[t*COUTC + c] * (rd0_b[c] + rd1_b[c]) + sp_w[c*9 + t] * rd2_b[c];
        }
        d_wg[t] = w;
        sK[t]   = k + w * rd3_b[0];
    }
    __syncthreads();
    if (tid < 9) {
        int rc = tid / 3, cc = tid % 3;
        float s = 0.f;
        for (int ty = 0; ty < 3; ++ty) {
            if ((rc == 0 && ty == 0) || (rc == 2 && ty == 2)) continue;
            for (int tx = 0; tx < 3; ++tx) {
                if ((cc == 0 && tx == 0) || (cc == 2 && tx == 2)) continue;
                s += sK[ty*3 + tx];
            }
        }
        d_Ksum[tid] = s;
    }
}

// ---------------------------------------------------------------------------
// Gated slabs: slab cb covers channels [32cb, 32cb+32); pure streaming reduce.
// ---------------------------------------------------------------------------
__device__ __forceinline__ void gated_part(const float* __restrict__ img,
                                           const float* __restrict__ rd3_w,
                                           int b) {
    __shared__ float sw[32];
    int pb = b % 176, cb = b / 176;
    int c0 = cb * 32;
    if (threadIdx.x < 32) sw[threadIdx.x] = rd3_w[c0 + threadIdx.x];
    __syncthreads();
    int p4 = pb * 256 + threadIdx.x;
    const float4* base = (const float4*)img + (size_t)c0 * (HW/4) + p4;
    float4 acc = make_float4(0.f, 0.f, 0.f, 0.f);
    #pragma unroll
    for (int c = 0; c < 32; ++c) {
        float w = sw[c];
        float4 x = __ldcs(base + (size_t)c * (HW/4));
        acc.x += w * x.x; acc.y += w * x.y; acc.z += w * x.z; acc.w += w * x.w;
    }
    d_gpart4[cb * (HW/4) + p4] = acc;
}

// ---------------------------------------------------------------------------
// Scatter, thread-per-point: feature row loaded once per point (float4),
// tap weights via smem float4 broadcasts, 9 spread atomicAdds per point.
// ---------------------------------------------------------------------------
template<int CF>
__device__ __forceinline__ void scatter_level(const float* __restrict__ feat,
                                              const float* __restrict__ coord,
                                              const int* __restrict__ grid,
                                              int N, const float* __restrict__ u,
                                              int blockInLevel) {
    constexpr int L  = CF + 3;
    constexpr int NC = CF/4 + 1;               // float4 chunks incl. coord tail
    __shared__ __align__(16) float4 suT[NC * 9];
    for (int idx = threadIdx.x; idx < NC * 9 * 4; idx += blockDim.x) {
        int c = idx & 3, jt = idx >> 2;
        int t = jt % 9, j = jt / 9;
        int i = 4 * j + c;
        ((float*)&suT[j * 9 + t])[c] = (i < L) ? u[t * L + i] : 0.f;
    }
    __syncthreads();
    int n = blockInLevel * 256 + threadIdx.x;
    if (n >= N) return;
    float acc[9];
    #pragma unroll
    for (int t = 0; t < 9; ++t) acc[t] = 0.f;
    const float4* fp = (const float4*)(feat + (size_t)n * CF);
    #pragma unroll
    for (int j = 0; j < CF/4; ++j) {
        float4 p = __ldg(fp + j);
        #pragma unroll
        for (int t = 0; t < 9; ++t) {
            float4 w = suT[j * 9 + t];
            acc[t] += w.x*p.x + w.y*p.y + w.z*p.z + w.w*p.w;
        }
    }
    float c0 = __ldg(coord + n*3 + 0);
    float c1 = __ldg(coord + n*3 + 1);
    float c2 = __ldg(coord + n*3 + 2);
    #pragma unroll
    for (int t = 0; t < 9; ++t) {
        float4 w = suT[(CF/4) * 9 + t];
        acc[t] += w.x*c0 + w.y*c1 + w.z*c2;
    }
    int2 gxy = __ldg((const int2*)grid + n);   // (col, row)
    #pragma unroll
    for (int t = 0; t < 9; ++t) {
        int h = gxy.y - t/3 + 1;
        int w = gxy.x - t%3 + 1;
        if (h >= 0 && h < Hh && w >= 0 && w < Ww)
            atomicAdd(&d_spt[h * Ww + w], acc[t]);
    }
}

#define GB 1408   // gated blocks (176 x 8)

// Combined gated + scatter. SCATTER BLOCKS FIRST: they begin immediately and
// overlap with the DRAM-bound gated stream instead of running as a tail.
__global__ void work_kernel(const float* __restrict__ img, const float* __restrict__ rd3_w,
                            const float* __restrict__ f0, const float* __restrict__ c0,
                            const int* __restrict__ g0, int N0,
                            const float* __restrict__ f1, const float* __restrict__ c1,
                            const int* __restrict__ g1, int N1,
                            const float* __restrict__ f2, const float* __restrict__ c2,
                            const int* __restrict__ g2, int N2,
                            int sb0, int sb1, int sb2) {
    int b = blockIdx.x;
    if (b < sb0) {
        scatter_level<32>(f0, c0, g0, N0, d_u0, b);
    } else if (b < sb0 + sb1) {
        scatter_level<64>(f1, c1, g1, N1, d_u1, b - sb0);
    } else if (b < sb0 + sb1 + sb2) {
        scatter_level<128>(f2, c2, g2, N2, d_v2, b - sb0 - sb1);
    } else {
        gated_part(img, rd3_w, b - sb0 - sb1 - sb2);
    }
}

// ---------------------------------------------------------------------------
// att: one row per block (176 threads). Sum 8 slabs for rows h-1..h+1 into a
// smem stencil buffer, then 9-tap with wg + boundary Ksum, sigmoid.
// ---------------------------------------------------------------------------
__global__ void att_kernel(const float* __restrict__ sp_b) {
    __shared__ __align__(16) float sm[3][712];   // cols at [4 .. 708)
    __shared__ float swg[9], sks[9];
    int h = blockIdx.x, t = threadIdx.x;
    if (t < 9)  swg[t] = d_wg[t];
    else if (t < 18) sks[t - 9] = d_Ksum[t - 9];
    #pragma unroll
    for (int r = 0; r < 3; ++r) {
        int y = h + r - 1;
        float4 s = make_float4(0.f, 0.f, 0.f, 0.f);
        if (y >= 0 && y < Hh) {
            #pragma unroll
            for (int sl = 0; sl < 8; ++sl) {
                float4 v = __ldg(&d_gpart4[sl * (HW/4) + y * W4 + t]);
                s.x += v.x; s.y += v.y; s.z += v.z; s.w += v.w;
            }
        }
        *(float4*)&sm[r][4 + 4*t] = s;
        if (t == 0) { sm[r][3] = 0.f; sm[r][708] = 0.f; }
    }
    __syncthreads();
    float bias = sp_b[0];
    int rc = (h == 0) ? 0 : (h == Hh-1 ? 2 : 1);
    float4 spt = ((const float4*)d_spt)[h * W4 + t];
    float sptv[4] = {spt.x, spt.y, spt.z, spt.w};
    float res[4];
    #pragma unroll
    for (int i = 0; i < 4; ++i) {
        int col = 4*t + i;
        int cc = (col == 0) ? 0 : (col == Ww-1 ? 2 : 1);
        float s = bias + sptv[i] + sks[rc*3 + cc];
        #pragma unroll
        for (int t9 = 0; t9 < 9; ++t9) {
            int dy = t9 / 3, dx = t9 % 3;
            s += swg[t9] * sm[dy][4 + col + dx - 1];
        }
        res[i] = 1.f / (1.f + __expf(-s));
    }
    d_att4[h * W4 + t] = make_float4(res[0], res[1], res[2], res[3]);
}

// ---------------------------------------------------------------------------
// out[c][p] = img[c][p] * att[p]; grid (176, 8), 32 channels per block.
// Fully unrolled for max MLP; .cs streaming both directions.
// ---------------------------------------------------------------------------
__global__ void mul_kernel(const float* __restrict__ img, float* __restrict__ out) {
    int p4 = blockIdx.x * 256 + threadIdx.x;
    float4 a = __ldg(&d_att4[p4]);
    size_t off = (size_t)blockIdx.y * 32 * (HW/4) + p4;
    const float4* img4 = (const float4*)img;
    float4* out4 = (float4*)out;
    #pragma unroll
    for (int c = 0; c < 32; ++c) {
        float4 v = __ldcs(&img4[off + (size_t)c * (HW/4)]);
        float4 r = make_float4(v.x * a.x, v.y * a.y, v.z * a.z, v.w * a.w);
        __stcs(&out4[off + (size_t)c * (HW/4)], r);
    }
}

extern "C" void kernel_launch(void* const* d_in, const int* in_sizes, int n_in,
                              void* d_out, int out_size) {
    const float* img   = (const float*)d_in[0];
    const float* f0    = (const float*)d_in[1];
    const float* c0    = (const float*)d_in[2];
    const int*   g0    = (const int*)  d_in[3];
    const float* f1    = (const float*)d_in[4];
    const float* c1    = (const float*)d_in[5];
    const int*   g1    = (const int*)  d_in[6];
    const float* f2    = (const float*)d_in[7];
    const float* c2    = (const float*)d_in[8];
    const int*   g2    = (const int*)  d_in[9];
    const float* rd0_w = (const float*)d_in[10];
    const float* rd0_b = (const float*)d_in[11];
    const float* rd1_w = (const float*)d_in[12];
    const float* rd1_b = (const float*)d_in[13];
    const float* rd2_w = (const float*)d_in[14];
    const float* rd2_b = (const float*)d_in[15];
    const float* rd3_w = (const float*)d_in[16];
    const float* rd3_b = (const float*)d_in[17];
    const float* sp_w  = (const float*)d_in[18];
    const float* sp_b  = (const float*)d_in[19];

    int N0 = in_sizes[1] / 32;
    int N1 = in_sizes[4] / 64;
    int N2 = in_sizes[7] / 128;
    int sb0 = (N0 + 255) / 256;
    int sb1 = (N1 + 255) / 256;
    int sb2 = (N2 + 255) / 256;

    setup_kernel<<<1 + (HW/4 + 511)/512, 512>>>(sp_w, rd0_w, rd1_w, rd0_b, rd1_b,
                                                rd2_w, rd2_b, rd3_b);
    work_kernel<<<sb0 + sb1 + sb2 + GB, 256>>>(img, rd3_w,
                                               f0, c0, g0, N0,
                                               f1, c1, g1, N1,
                                               f2, c2, g2, N2,
                                               sb0, sb1, sb2);
    att_kernel<<<Hh, 176>>>(sp_b);
    mul_kernel<<<dim3(176, 8), 256>>>(img, (float*)d_out);
}